// round 11
// baseline (speedup 1.0000x reference)
#include <cuda_runtime.h>
#include <cuda_bf16.h>
#include <cuda_fp16.h>
#include <math.h>
#include <stdint.h>

#define Bc   32
#define Ssz  201
#define SL   200
#define Hdim 512
#define Vdim 32000
#define Mrows (Bc*SL)   // 6400

// ---------------- scratch (static device globals; no allocation) ------------
__device__ __align__(16) float g_hidden[Mrows*Hdim];
__device__ __align__(16) float g_depend[Mrows*Hdim];
__device__ __align__(16) float g_enc   [Mrows*Hdim];
__device__ __align__(16) float g_map1  [Mrows*Hdim];
__device__ __align__(16) float g_ti    [Mrows*Hdim];
__device__ int g_caslen[Bc];

// bf16 split activations (hi/lo)
__device__ __align__(16) __nv_bfloat16 g_emb_hi[Mrows*Hdim];
__device__ __align__(16) __nv_bfloat16 g_emb_lo[Mrows*Hdim];
__device__ __align__(16) __nv_bfloat16 g_tw_hi [Mrows*Hdim];
__device__ __align__(16) __nv_bfloat16 g_tw_lo [Mrows*Hdim];
__device__ __align__(16) __nv_bfloat16 g_hid_hi[Mrows*Hdim];
__device__ __align__(16) __nv_bfloat16 g_hid_lo[Mrows*Hdim];
__device__ __align__(16) __nv_bfloat16 g_hed_hi[Mrows*Hdim];
__device__ __align__(16) __nv_bfloat16 g_hed_lo[Mrows*Hdim];
__device__ __align__(16) __nv_bfloat16 g_tal_hi[Mrows*Hdim];
__device__ __align__(16) __nv_bfloat16 g_tal_lo[Mrows*Hdim];
__device__ __align__(16) __nv_bfloat16 g_dep_hi[Mrows*Hdim];
__device__ __align__(16) __nv_bfloat16 g_dep_lo[Mrows*Hdim];
__device__ __align__(16) __nv_bfloat16 g_enc_hi[Mrows*Hdim];
__device__ __align__(16) __nv_bfloat16 g_enc_lo[Mrows*Hdim];

// hidden transposed per batch: [b][h][jpad=256] (zero-init covers pad)
__device__ __align__(16) __nv_bfloat16 g_hidT_h[Bc*Hdim*256];
__device__ __align__(16) __nv_bfloat16 g_hidT_l[Bc*Hdim*256];

// bf16 split transposed weights [N, K] K-major
__device__ __align__(16) __nv_bfloat16 g_w1T_h [Hdim*Hdim];
__device__ __align__(16) __nv_bfloat16 g_w1T_l [Hdim*Hdim];
__device__ __align__(16) __nv_bfloat16 g_whtT_h[2*Hdim*Hdim];  // [1024, 512] wh|wt stacked
__device__ __align__(16) __nv_bfloat16 g_whtT_l[2*Hdim*Hdim];
__device__ __align__(16) __nv_bfloat16 g_wm1T_h[Hdim*Hdim];
__device__ __align__(16) __nv_bfloat16 g_wm1T_l[Hdim*Hdim];
__device__ __align__(16) __nv_bfloat16 g_wtiT_h[Hdim*Hdim];
__device__ __align__(16) __nv_bfloat16 g_wtiT_l[Hdim*Hdim];
__device__ __align__(16) __nv_bfloat16 g_wgT_h [Hdim*2*Hdim];
__device__ __align__(16) __nv_bfloat16 g_wgT_l [Hdim*2*Hdim];
__device__ __align__(16) float g_bht[2*Hdim];   // bh|bt stacked

// fp16 operands for the final 1-term GEMM
__device__ __align__(16) __half g_a16[Mrows*Hdim];
__device__ __align__(16) __half g_w16[(size_t)Vdim*Hdim];   // [V, H] K-major

__device__ __forceinline__ float elu_f(float x){ return x > 0.f ? x : (expf(x) - 1.f); }

// ========================= mma helpers =====================================
__device__ __forceinline__ uint32_t smem_u32(const void* p){
    uint32_t a;
    asm("{ .reg .u64 t; cvta.to.shared.u64 t, %1; cvt.u32.u64 %0, t; }" : "=r"(a) : "l"(p));
    return a;
}
#define SWZ128(off) ((off) ^ (((off) >> 3) & 0x70))

__device__ __forceinline__ void cpa16(uint32_t s, const void* g){
    asm volatile("cp.async.cg.shared.global [%0], [%1], 16;" :: "r"(s), "l"(g));
}

#define LDSM4(r0, r1, r2, r3, addr) \
    asm volatile("ldmatrix.sync.aligned.m8n8.x4.shared.b16 {%0,%1,%2,%3}, [%4];" \
        : "=r"(r0), "=r"(r1), "=r"(r2), "=r"(r3) : "r"(addr))

#define MMABF(c, a, b0, b1) \
    asm volatile("mma.sync.aligned.m16n8k16.row.col.f32.bf16.bf16.f32 " \
        "{%0,%1,%2,%3},{%4,%5,%6,%7},{%8,%9},{%0,%1,%2,%3};" \
        : "+f"((c)[0]), "+f"((c)[1]), "+f"((c)[2]), "+f"((c)[3]) \
        : "r"((a)[0]), "r"((a)[1]), "r"((a)[2]), "r"((a)[3]), "r"(b0), "r"(b1))

#define MMAFP(c, a, b0, b1) \
    asm volatile("mma.sync.aligned.m16n8k16.row.col.f32.f16.f16.f32 " \
        "{%0,%1,%2,%3},{%4,%5,%6,%7},{%8,%9},{%0,%1,%2,%3};" \
        : "+f"((c)[0]), "+f"((c)[1]), "+f"((c)[2]), "+f"((c)[3]) \
        : "r"((a)[0]), "r"((a)[1]), "r"((a)[2]), "r"((a)[3]), "r"(b0), "r"(b1))

// ---------------- cas_len -----------------------------------------------
__global__ void caslen_k(const int* __restrict__ cas){
    int b = blockIdx.x, tid = threadIdx.x;
    int c = (tid < SL && cas[b*Ssz + tid] != 0) ? 1 : 0;
    for (int o = 16; o; o >>= 1) c += __shfl_xor_sync(0xffffffffu, c, o);
    __shared__ int s[8];
    if ((tid & 31) == 0) s[tid >> 5] = c;
    __syncthreads();
    if (tid == 0) { int t = 0; for (int q = 0; q < 8; q++) t += s[q]; g_caslen[b] = t; }
}

__global__ void concatBias_k(const float* __restrict__ bh, const float* __restrict__ bt){
    int i = threadIdx.x + blockIdx.x*256;
    g_bht[i] = (i < Hdim) ? bh[i] : bt[i - Hdim];
}

// ---------------- weight transpose + split -------------------------------
__global__ void transW_bf16_k(const float* __restrict__ w,
                              __nv_bfloat16* __restrict__ hi,
                              __nv_bfloat16* __restrict__ lo, int Kdim){
    __shared__ float t[32][33];
    int n0 = blockIdx.x*32, k0 = blockIdx.y*32;
    int x = threadIdx.x, y = threadIdx.y;
    for (int i = y; i < 32; i += 8)
        t[i][x] = w[(size_t)(k0+i)*Hdim + n0 + x];
    __syncthreads();
    for (int nn = y; nn < 32; nn += 8) {
        float v = t[x][nn];
        __nv_bfloat16 h = __float2bfloat16(v);
        size_t o = (size_t)(n0+nn)*Kdim + k0 + x;
        hi[o] = h;
        lo[o] = __float2bfloat16(v - __bfloat162float(h));
    }
}

__global__ void transW_f16_k(const float* __restrict__ w, __half* __restrict__ out){
    __shared__ float t[32][33];
    int n0 = blockIdx.x*32, k0 = blockIdx.y*32;
    int x = threadIdx.x, y = threadIdx.y;
    for (int i = y; i < 32; i += 8)
        t[i][x] = w[(size_t)(k0+i)*Vdim + n0 + x];
    __syncthreads();
    for (int nn = y; nn < 32; nn += 8)
        out[(size_t)(n0+nn)*Hdim + k0 + x] = __float2half(t[x][nn]);
}

__global__ void gatherSplit_k(const float* __restrict__ table, const int* __restrict__ idx,
                              __nv_bfloat16* __restrict__ hi, __nv_bfloat16* __restrict__ lo){
    int i = blockIdx.x*256 + threadIdx.x;
    int r = i >> 9, c = i & 511;
    int row = idx[(r/SL)*Ssz + (r%SL)];
    float v = table[(size_t)row*Hdim + c];
    __nv_bfloat16 h = __float2bfloat16(v);
    hi[i] = h;
    lo[i] = __float2bfloat16(v - __bfloat162float(h));
}

// hidden [b*SL+j][h] -> hidT hi/lo [b][h][256]
__global__ void transHid_k(){
    __shared__ float t[32][33];
    int b = blockIdx.z;
    int j0 = blockIdx.x*32, h0 = blockIdx.y*32;
    int x = threadIdx.x, y = threadIdx.y;
    for (int i = y; i < 32; i += 8) {
        int j = j0 + i;
        t[i][x] = (j < SL) ? g_hidden[(size_t)(b*SL + j)*Hdim + h0 + x] : 0.f;
    }
    __syncthreads();
    for (int hh = y; hh < 32; hh += 8) {
        float v = t[x][hh];
        __nv_bfloat16 h = __float2bfloat16(v);
        size_t o = ((size_t)(b*Hdim + h0 + hh))*256 + j0 + x;
        g_hidT_h[o] = h;
        g_hidT_l[o] = __float2bfloat16(v - __bfloat162float(h));
    }
}

// ---------------- mid bf16 3-term mma GEMM -------------------------------
// single-buffered 64KB stage, 2 CTAs/SM (cross-CTA overlap), tile 128x128
#define MGM 128
#define MGN 128
#define MKC 64
#define MOFF_AH 0
#define MOFF_AL 16384
#define MOFF_BH 32768
#define MOFF_BL 49152
#define SMEM_MG 65536

// EPI: 0 bias; 1 bias+elu+mask+splits; 2 bias+elu; 3 gate-combine+mask+splits;
//      5 bias+splits into head(c<512)/tail(c>=512)
template<int EPI>
__device__ __forceinline__ void epi_store(float v, int r, int c,
    const float* __restrict__ bias, float* __restrict__ C,
    __nv_bfloat16* __restrict__ Chi, __nv_bfloat16* __restrict__ Clo)
{
    v += bias[c];
    if (EPI == 1 || EPI == 2) v = elu_f(v);
    if (EPI == 3) {
        float g = 1.f / (1.f + expf(-v));
        float h = g_hidden[(size_t)r*Hdim + c];
        float d = g_depend[(size_t)r*Hdim + c];
        v = g*h + (1.f - g)*d;
    }
    if (EPI == 1 || EPI == 3) {
        int bb = r / SL, ii = r % SL;
        if (ii >= g_caslen[bb]) v = 0.f;
    }
    if (EPI == 5) {
        __nv_bfloat16 h = __float2bfloat16(v);
        __nv_bfloat16 l = __float2bfloat16(v - __bfloat162float(h));
        if (c < Hdim) {
            g_hed_hi[(size_t)r*Hdim + c] = h;
            g_hed_lo[(size_t)r*Hdim + c] = l;
        } else {
            g_tal_hi[(size_t)r*Hdim + c - Hdim] = h;
            g_tal_lo[(size_t)r*Hdim + c - Hdim] = l;
        }
        return;
    }
    C[(size_t)r*Hdim + c] = v;
    if (EPI == 1 || EPI == 3) {
        __nv_bfloat16 h = __float2bfloat16(v);
        Chi[(size_t)r*Hdim + c] = h;
        Clo[(size_t)r*Hdim + c] = __float2bfloat16(v - __bfloat162float(h));
    }
}

template<int EPI>
__global__ __launch_bounds__(256, 2) void mgemm_k(
    const __nv_bfloat16* __restrict__ Ah0, const __nv_bfloat16* __restrict__ Al0,
    const __nv_bfloat16* __restrict__ Ah1, const __nv_bfloat16* __restrict__ Al1,
    const __nv_bfloat16* __restrict__ Wh,  const __nv_bfloat16* __restrict__ Wl,
    int ldw, int nkc,
    const float* __restrict__ bias, float* __restrict__ C,
    __nv_bfloat16* __restrict__ Chi, __nv_bfloat16* __restrict__ Clo)
{
    extern __shared__ char smem[];
    const int tid = threadIdx.x, lane = tid & 31, wid = tid >> 5;
    const int bn = blockIdx.x, bm = blockIdx.y;
    const int wm = wid & 1, wn = wid >> 1;
    const int rl = lane & 15, gl = lane >> 4;
    uint32_t sb = smem_u32(smem);

    float acc[4][4][4];
    #pragma unroll
    for (int mi = 0; mi < 4; mi++)
        #pragma unroll
        for (int ni = 0; ni < 4; ni++)
            #pragma unroll
            for (int q = 0; q < 4; q++) acc[mi][ni][q] = 0.f;

    for (int kc = 0; kc < nkc; kc++) {
        {   // load stage (single buffer)
            const __nv_bfloat16 *ah, *al; int koff;
            if (kc < 8) { ah = Ah0; al = Al0; koff = kc*MKC; }
            else        { ah = Ah1; al = Al1; koff = (kc-8)*MKC; }
            const __nv_bfloat16* ap_h = ah + (size_t)(bm*MGM)*Hdim + koff;
            const __nv_bfloat16* ap_l = al + (size_t)(bm*MGM)*Hdim + koff;
            const __nv_bfloat16* wp_h = Wh + (size_t)(bn*MGN)*ldw + kc*MKC;
            const __nv_bfloat16* wp_l = Wl + (size_t)(bn*MGN)*ldw + kc*MKC;
            #pragma unroll
            for (int t = 0; t < 4; t++) {
                int G = tid + t*256; int r = G >> 3, g = G & 7;
                uint32_t d = SWZ128((uint32_t)(r*128 + g*16));
                cpa16(sb + MOFF_AH + d, ap_h + (size_t)r*Hdim + g*8);
                cpa16(sb + MOFF_AL + d, ap_l + (size_t)r*Hdim + g*8);
                cpa16(sb + MOFF_BH + d, wp_h + (size_t)r*ldw + g*8);
                cpa16(sb + MOFF_BL + d, wp_l + (size_t)r*ldw + g*8);
            }
            asm volatile("cp.async.commit_group;" ::: "memory");
        }
        asm volatile("cp.async.wait_group 0;" ::: "memory");
        __syncthreads();

        #pragma unroll
        for (int ks = 0; ks < 4; ks++) {
            const int kg = 2*ks + gl;
            uint32_t Aa[4][4], Bb[2][4], Al2[4][4];
            #pragma unroll
            for (int mi = 0; mi < 4; mi++) {
                uint32_t ad = sb + MOFF_AH + SWZ128((uint32_t)((wm*64 + mi*16 + rl)*128 + kg*16));
                LDSM4(Aa[mi][0], Aa[mi][1], Aa[mi][2], Aa[mi][3], ad);
            }
            #pragma unroll
            for (int np = 0; np < 2; np++) {
                uint32_t bd = sb + MOFF_BH + SWZ128((uint32_t)((wn*32 + np*16 + rl)*128 + kg*16));
                LDSM4(Bb[np][0], Bb[np][1], Bb[np][2], Bb[np][3], bd);
            }
            #pragma unroll
            for (int mi = 0; mi < 4; mi++)
                #pragma unroll
                for (int np = 0; np < 2; np++) {
                    MMABF(acc[mi][2*np  ], Aa[mi], Bb[np][0], Bb[np][2]);
                    MMABF(acc[mi][2*np+1], Aa[mi], Bb[np][1], Bb[np][3]);
                }
            #pragma unroll
            for (int mi = 0; mi < 4; mi++) {
                uint32_t ad = sb + MOFF_AL + SWZ128((uint32_t)((wm*64 + mi*16 + rl)*128 + kg*16));
                LDSM4(Al2[mi][0], Al2[mi][1], Al2[mi][2], Al2[mi][3], ad);
            }
            #pragma unroll
            for (int mi = 0; mi < 4; mi++)
                #pragma unroll
                for (int np = 0; np < 2; np++) {
                    MMABF(acc[mi][2*np  ], Al2[mi], Bb[np][0], Bb[np][2]);
                    MMABF(acc[mi][2*np+1], Al2[mi], Bb[np][1], Bb[np][3]);
                }
            #pragma unroll
            for (int np = 0; np < 2; np++) {
                uint32_t bd = sb + MOFF_BL + SWZ128((uint32_t)((wn*32 + np*16 + rl)*128 + kg*16));
                LDSM4(Bb[np][0], Bb[np][1], Bb[np][2], Bb[np][3], bd);
            }
            #pragma unroll
            for (int mi = 0; mi < 4; mi++)
                #pragma unroll
                for (int np = 0; np < 2; np++) {
                    MMABF(acc[mi][2*np  ], Aa[mi], Bb[np][0], Bb[np][2]);
                    MMABF(acc[mi][2*np+1], Aa[mi], Bb[np][1], Bb[np][3]);
                }
        }
        __syncthreads();
    }

    const int mbase = bm*MGM + wm*64 + (lane >> 2);
    const int nbase = bn*MGN + wn*32 + 2*(lane & 3);
    #pragma unroll
    for (int mi = 0; mi < 4; mi++) {
        int r0 = mbase + mi*16, r1 = r0 + 8;
        #pragma unroll
        for (int ni = 0; ni < 4; ni++) {
            int n = nbase + ni*8;
            epi_store<EPI>(acc[mi][ni][0], r0, n,   bias, C, Chi, Clo);
            epi_store<EPI>(acc[mi][ni][1], r0, n+1, bias, C, Chi, Clo);
            epi_store<EPI>(acc[mi][ni][2], r1, n,   bias, C, Chi, Clo);
            epi_store<EPI>(acc[mi][ni][3], r1, n+1, bias, C, Chi, Clo);
        }
    }
}

// ---------------- attention via mma --------------------------------------
#define AT_S_HI 0
#define AT_S_LO 32768
#define AT_STG  65536
#define AT_RED  (AT_STG + 131072)
#define SMEM_AT (196608 + 2048)

__global__ __launch_bounds__(256) void attnmma_k()
{
    extern __shared__ char smem[];
    const int tid = threadIdx.x, lane = tid & 31, wid = tid >> 5;
    const int t = blockIdx.x, b = blockIdx.y;
    const int len = g_caslen[b];
    const int rl = lane & 15, gl = lane >> 4;
    uint32_t sb = smem_u32(smem);
    const uint32_t stg = sb + AT_STG;
    float* red = (float*)(smem + AT_RED);

    float acc1[4][4][4];
    #pragma unroll
    for (int mi = 0; mi < 4; mi++)
        #pragma unroll
        for (int ni = 0; ni < 4; ni++)
            #pragma unroll
            for (int q = 0; q < 4; q++) acc1[mi][ni][q] = 0.f;

    for (int kc = 0; kc < 8; kc++) {
        #pragma unroll
        for (int q = 0; q < 2; q++) {
            int G = tid + q*256; int r = G >> 3, g = G & 7;
            int gi = t*64 + r; if (gi >= SL) gi = SL-1;
            size_t go = (size_t)(b*SL + gi)*Hdim + kc*64 + g*8;
            uint32_t d = SWZ128((uint32_t)(r*128 + g*16));
            cpa16(stg + 0    + d, g_hed_hi + go);
            cpa16(stg + 8192 + d, g_hed_lo + go);
        }
        #pragma unroll
        for (int q = 0; q < 8; q++) {
            int G = tid + q*256; int r = G >> 3, g = G & 7;
            int gj = (r < SL) ? r : SL-1;
            size_t go = (size_t)(b*SL + gj)*Hdim + kc*64 + g*8;
            uint32_t d = SWZ128((uint32_t)(r*128 + g*16));
            cpa16(stg + 16384 + d, g_tal_hi + go);
            cpa16(stg + 49152 + d, g_tal_lo + go);
        }
        asm volatile("cp.async.commit_group;" ::: "memory");
        asm volatile("cp.async.wait_group 0;" ::: "memory");
        __syncthreads();

        #pragma unroll
        for (int ks = 0; ks < 4; ks++) {
            const int kg = 2*ks + gl;
            uint32_t Aa[4][4], Bb[2][4], Al2[4][4];
            #pragma unroll
            for (int mi = 0; mi < 4; mi++) {
                uint32_t ad = stg + 0 + SWZ128((uint32_t)((mi*16 + rl)*128 + kg*16));
                LDSM4(Aa[mi][0], Aa[mi][1], Aa[mi][2], Aa[mi][3], ad);
            }
            #pragma unroll
            for (int np = 0; np < 2; np++) {
                uint32_t bd = stg + 16384 + SWZ128((uint32_t)((wid*32 + np*16 + rl)*128 + kg*16));
                LDSM4(Bb[np][0], Bb[np][1], Bb[np][2], Bb[np][3], bd);
            }
            #pragma unroll
            for (int mi = 0; mi < 4; mi++)
                #pragma unroll
                for (int np = 0; np < 2; np++) {
                    MMABF(acc1[mi][2*np  ], Aa[mi], Bb[np][0], Bb[np][2]);
                    MMABF(acc1[mi][2*np+1], Aa[mi], Bb[np][1], Bb[np][3]);
                }
            #pragma unroll
            for (int mi = 0; mi < 4; mi++) {
                uint32_t ad = stg + 8192 + SWZ128((uint32_t)((mi*16 + rl)*128 + kg*16));
                LDSM4(Al2[mi][0], Al2[mi][1], Al2[mi][2], Al2[mi][3], ad);
            }
            #pragma unroll
            for (int mi = 0; mi < 4; mi++)
                #pragma unroll
                for (int np = 0; np < 2; np++) {
                    MMABF(acc1[mi][2*np  ], Al2[mi], Bb[np][0], Bb[np][2]);
                    MMABF(acc1[mi][2*np+1], Al2[mi], Bb[np][1], Bb[np][3]);
                }
            #pragma unroll
            for (int np = 0; np < 2; np++) {
                uint32_t bd = stg + 49152 + SWZ128((uint32_t)((wid*32 + np*16 + rl)*128 + kg*16));
                LDSM4(Bb[np][0], Bb[np][1], Bb[np][2], Bb[np][3], bd);
            }
            #pragma unroll
            for (int mi = 0; mi < 4; mi++)
                #pragma unroll
                for (int np = 0; np < 2; np++) {
                    MMABF(acc1[mi][2*np  ], Aa[mi], Bb[np][0], Bb[np][2]);
                    MMABF(acc1[mi][2*np+1], Aa[mi], Bb[np][1], Bb[np][3]);
                }
        }
        __syncthreads();
    }

    const int rbase = lane >> 2, cbase = 2*(lane & 3);
    float rmax[4][2];
    #pragma unroll
    for (int mi = 0; mi < 4; mi++)
        #pragma unroll
        for (int qh = 0; qh < 2; qh++) {
            int ig = t*64 + mi*16 + rbase + 8*qh;
            float m = -1e30f;
            #pragma unroll
            for (int ni = 0; ni < 4; ni++)
                #pragma unroll
                for (int q0 = 0; q0 < 2; q0++) {
                    int jg = wid*32 + ni*8 + cbase + q0;
                    float v = acc1[mi][ni][qh*2 + q0];
                    if (jg < ig && jg < len) m = fmaxf(m, v);
                }
            m = fmaxf(m, __shfl_xor_sync(0xffffffffu, m, 1));
            m = fmaxf(m, __shfl_xor_sync(0xffffffffu, m, 2));
            rmax[mi][qh] = m;
            if ((lane & 3) == 0) red[(mi*16 + rbase + 8*qh)*8 + wid] = m;
        }
    __syncthreads();
    #pragma unroll
    for (int mi = 0; mi < 4; mi++)
        #pragma unroll
        for (int qh = 0; qh < 2; qh++) {
            float m = -1e30f;
            int row = mi*16 + rbase + 8*qh;
            #pragma unroll
            for (int w = 0; w < 8; w++) m = fmaxf(m, red[row*8 + w]);
            rmax[mi][qh] = m;
        }
    __syncthreads();

    float rsum[4][2];
    #pragma unroll
    for (int mi = 0; mi < 4; mi++)
        #pragma unroll
        for (int qh = 0; qh < 2; qh++) {
            int ig = t*64 + mi*16 + rbase + 8*qh;
            float s = 0.f;
            #pragma unroll
            for (int ni = 0; ni < 4; ni++)
                #pragma unroll
                for (int q0 = 0; q0 < 2; q0++) {
                    int jg = wid*32 + ni*8 + cbase + q0;
                    float v = acc1[mi][ni][qh*2 + q0];
                    float e = (jg < ig && jg < len) ? expf(v - rmax[mi][qh]) : 0.f;
                    acc1[mi][ni][qh*2 + q0] = e;
                    s += e;
                }
            s += __shfl_xor_sync(0xffffffffu, s, 1);
            s += __shfl_xor_sync(0xffffffffu, s, 2);
            if ((lane & 3) == 0) red[(mi*16 + rbase + 8*qh)*8 + wid] = s;
        }
    __syncthreads();
    #pragma unroll
    for (int mi = 0; mi < 4; mi++)
        #pragma unroll
        for (int qh = 0; qh < 2; qh++) {
            float s = 0.f;
            int row = mi*16 + rbase + 8*qh;
            #pragma unroll
            for (int w = 0; w < 8; w++) s += red[row*8 + w];
            rsum[mi][qh] = (s > 0.f) ? 1.f/s : 0.f;
        }

    #pragma unroll
    for (int mi = 0; mi < 4; mi++)
        #pragma unroll
        for (int qh = 0; qh < 2; qh++) {
            int row = mi*16 + rbase + 8*qh;
            #pragma unroll
            for (int ni = 0; ni < 4; ni++)
                #pragma unroll
                for (int q0 = 0; q0 < 2; q0++) {
                    int jg = wid*32 + ni*8 + cbase + q0;
                    float p = acc1[mi][ni][qh*2 + q0] * rsum[mi][qh];
                    __nv_bfloat16 ph = __float2bfloat16(p);
                    __nv_bfloat16 pl = __float2bfloat16(p - __bfloat162float(ph));
                    int chunk = jg >> 6, col = jg & 63;
                    uint32_t off = chunk*8192 + SWZ128((uint32_t)(row*128 + col*2));
                    uint16_t uh = *(uint16_t*)&ph, ul = *(uint16_t*)&pl;
                    asm volatile("st.shared.b16 [%0], %1;" :: "r"(sb + AT_S_HI + off), "h"(uh));
                    asm volatile("st.shared.b16 [%0], %1;" :: "r"(sb + AT_S_LO + off), "h"(ul));
                }
        }
    __syncthreads();

    float acc2[4][8][4];
    #pragma unroll
    for (int mi = 0; mi < 4; mi++)
        #pragma unroll
        for (int nj = 0; nj < 8; nj++)
            #pragma unroll
            for (int q = 0; q < 4; q++) acc2[mi][nj][q] = 0.f;

    for (int kc = 0; kc < 4; kc++) {
        #pragma unroll
        for (int q = 0; q < 16; q++) {
            int G = tid + q*256; int r = G >> 3, g = G & 7;
            size_t go = ((size_t)(b*Hdim + r))*256 + kc*64 + g*8;
            uint32_t d = SWZ128((uint32_t)(r*128 + g*16));
            cpa16(stg + 0     + d, g_hidT_h + go);
            cpa16(stg + 65536 + d, g_hidT_l + go);
        }
        asm volatile("cp.async.commit_group;" ::: "memory");
        asm volatile("cp.async.wait_group 0;" ::: "memory");
        __syncthreads();

        #pragma unroll
        for (int ks = 0; ks < 4; ks++) {
            const int kg = 2*ks + gl;
            uint32_t Aa[4][4], Bb[4][4], Al2[4][4];
            #pragma unroll
            for (int mi = 0; mi < 4; mi++) {
                uint32_t ad = sb + AT_S_HI + kc*8192 + SWZ128((uint32_t)((mi*16 + rl)*128 + kg*16));
                LDSM4(Aa[mi][0], Aa[mi][1], Aa[mi][2], Aa[mi][3], ad);
            }
            #pragma unroll
            for (int np = 0; np < 4; np++) {
                uint32_t bd = stg + 0 + SWZ128((uint32_t)((wid*64 + np*16 + rl)*128 + kg*16));
                LDSM4(Bb[np][0], Bb[np][1], Bb[np][2], Bb[np][3], bd);
            }
            #pragma unroll
            for (int mi = 0; mi < 4; mi++)
                #pragma unroll
                for (int np = 0; np < 4; np++) {
                    MMABF(acc2[mi][2*np  ], Aa[mi], Bb[np][0], Bb[np][2]);
                    MMABF(acc2[mi][2*np+1], Aa[mi], Bb[np][1], Bb[np][3]);
                }
            #pragma unroll
            for (int mi = 0; mi < 4; mi++) {
                uint32_t ad = sb + AT_S_LO + kc*8192 + SWZ128((uint32_t)((mi*16 + rl)*128 + kg*16));
                LDSM4(Al2[mi][0], Al2[mi][1], Al2[mi][2], Al2[mi][3], ad);
            }
            #pragma unroll
            for (int mi = 0; mi < 4; mi++)
                #pragma unroll
                for (int np = 0; np < 4; np++) {
                    MMABF(acc2[mi][2*np  ], Al2[mi], Bb[np][0], Bb[np][2]);
                    MMABF(acc2[mi][2*np+1], Al2[mi], Bb[np][1], Bb[np][3]);
                }
            #pragma unroll
            for (int np = 0; np < 4; np++) {
                uint32_t bd = stg + 65536 + SWZ128((uint32_t)((wid*64 + np*16 + rl)*128 + kg*16));
                LDSM4(Bb[np][0], Bb[np][1], Bb[np][2], Bb[np][3], bd);
            }
            #pragma unroll
            for (int mi = 0; mi < 4; mi++)
                #pragma unroll
                for (int np = 0; np < 4; np++) {
                    MMABF(acc2[mi][2*np  ], Aa[mi], Bb[np][0], Bb[np][2]);
                    MMABF(acc2[mi][2*np+1], Aa[mi], Bb[np][1], Bb[np][3]);
                }
        }
        __syncthreads();
    }

    #pragma unroll
    for (int mi = 0; mi < 4; mi++)
        #pragma unroll
        for (int qh = 0; qh < 2; qh++) {
            int ig = t*64 + mi*16 + rbase + 8*qh;
            if (ig >= SL) continue;
            size_t rowo = (size_t)(b*SL + ig)*Hdim;
            #pragma unroll
            for (int nj = 0; nj < 8; nj++)
                #pragma unroll
                for (int q0 = 0; q0 < 2; q0++) {
                    int h = wid*64 + nj*8 + cbase + q0;
                    float v = acc2[mi][nj][qh*2 + q0];
                    g_depend[rowo + h] = v;
                    __nv_bfloat16 vh = __float2bfloat16(v);
                    g_dep_hi[rowo + h] = vh;
                    g_dep_lo[rowo + h] = __float2bfloat16(v - __bfloat162float(vh));
                }
        }
}

// ---------------- pool ---------------------------------------------------
__global__ __launch_bounds__(256) void pool_k(
    const float* __restrict__ wm2, const float* __restrict__ bm2)
{
    int b = blockIdx.x, tid = threadIdx.x, w = tid >> 5, l = tid & 31;
    __shared__ float m2[SL];
    __shared__ float red[8];
    int len = g_caslen[b];

    for (int i = w; i < SL; i += 8) {
        size_t r = (size_t)b*SL + i;
        float s = 0.f;
        #pragma unroll 4
        for (int h = l; h < Hdim; h += 32)
            s = fmaf(g_map1[r*Hdim + h] * g_ti[r*Hdim + h], wm2[h], s);
        for (int o = 16; o; o >>= 1) s += __shfl_xor_sync(0xffffffffu, s, o);
        if (l == 0) m2[i] = s + bm2[0];
    }
    __syncthreads();

    float mx = -1e30f;
    for (int i = tid; i < len; i += 256) mx = fmaxf(mx, m2[i]);
    for (int o = 16; o; o >>= 1) mx = fmaxf(mx, __shfl_xor_sync(0xffffffffu, mx, o));
    if (l == 0) red[w] = mx;
    __syncthreads();
    if (tid == 0) { float mm = red[0]; for (int q = 1; q < 8; q++) mm = fmaxf(mm, red[q]); red[0] = mm; }
    __syncthreads();
    mx = red[0];

    float sum = 0.f;
    for (int i = tid; i < len; i += 256) { float e = expf(m2[i] - mx); m2[i] = e; sum += e; }
    for (int o = 16; o; o >>= 1) sum += __shfl_xor_sync(0xffffffffu, sum, o);
    __syncthreads();
    if (l == 0) red[w] = sum;
    __syncthreads();
    if (tid == 0) { float t = 0.f; for (int q = 0; q < 8; q++) t += red[q]; red[0] = t; }
    __syncthreads();
    float inv = (len > 0) ? 1.f / red[0] : 0.f;

    for (int i = tid; i < SL; i += 256) m2[i] = (i < len) ? m2[i]*inv : 0.f;
    __syncthreads();

    size_t base = (size_t)b*SL*Hdim;
    for (int e = tid; e < SL*Hdim; e += 256) {
        int i = e >> 9;
        g_a16[base + e] = __float2half(m2[i] * g_enc[base + e]);
    }
}

// ---------------- final fp16 GEMM: tile 128x256, warp 64x64 --------------
#define FOFF_B 16384
#define FSTG 49152
#define SMEM_FG (2*FSTG)   // 98304

__device__ __forceinline__ void load_fin(uint32_t base, const __half* A, const __half* W, int tid){
    #pragma unroll
    for (int t = 0; t < 4; t++) {       // A: 128 rows
        int G = tid + t*256; int r = G >> 3, g = G & 7;
        uint32_t d = SWZ128((uint32_t)(r*128 + g*16));
        cpa16(base + d, A + (size_t)r*Hdim + g*8);
    }
    #pragma unroll
    for (int t = 0; t < 8; t++) {       // B: 256 rows
        int G = tid + t*256; int r = G >> 3, g = G & 7;
        uint32_t d = SWZ128((uint32_t)(r*128 + g*16));
        cpa16(base + FOFF_B + d, W + (size_t)r*Hdim + g*8);
    }
    asm volatile("cp.async.commit_group;" ::: "memory");
}

__global__ __launch_bounds__(256, 1) void fgemm_k(
    const float* __restrict__ bias, float* __restrict__ C)
{
    extern __shared__ char smem[];
    const int tid = threadIdx.x, lane = tid & 31, wid = tid >> 5;
    const int bn = blockIdx.x, bm = blockIdx.y;
    const int wm = wid & 1, wn = wid >> 1;   // 2(M) x 4(N), warp tile 64x64
    const int rl = lane & 15, gl = lane >> 4;
    uint32_t sb = smem_u32(smem);

    float acc[4][8][4];
    #pragma unroll
    for (int mi = 0; mi < 4; mi++)
        #pragma unroll
        for (int nj = 0; nj < 8; nj++)
            #pragma unroll
            for (int q = 0; q < 4; q++) acc[mi][nj][q] = 0.f;

    const __half* A0 = g_a16 + (size_t)(bm*128)*Hdim;
    const __half* W0 = g_w16 + (size_t)(bn*256)*Hdim;

    load_fin(sb,        A0,      W0,      tid);
    load_fin(sb + FSTG, A0 + 64, W0 + 64, tid);

    for (int kc = 0; kc < 8; kc++) {
        if (kc < 7) asm volatile("cp.async.wait_group 1;" ::: "memory");
        else        asm volatile("cp.async.wait_group 0;" ::: "memory");
        __syncthreads();
        const uint32_t base = sb + (kc & 1)*FSTG;
        #pragma unroll
        for (int ks = 0; ks < 4; ks++) {
            const int kg = 2*ks + gl;
            uint32_t Aa[4][4], Bb[4][4];
            #pragma unroll
            for (int mi = 0; mi < 4; mi++) {
                uint32_t ad = base + SWZ128((uint32_t)((wm*64 + mi*16 + rl)*128 + kg*16));
                LDSM4(Aa[mi][0], Aa[mi][1], Aa[mi][2], Aa[mi][3], ad);
            }
            #pragma unroll
            for (int np = 0; np < 4; np++) {
                uint32_t bd = base + FOFF_B + SWZ128((uint32_t)((wn*64 + np*16 + rl)*128 + kg*16));
                LDSM4(Bb[np][0], Bb[np][1], Bb[np][2], Bb[np][3], bd);
            }
            #pragma unroll
            for (int mi = 0; mi < 4; mi++)
                #pragma unroll
                for (int np = 0; np < 4; np++) {
                    MMAFP(acc[mi][2*np  ], Aa[mi], Bb[np][0], Bb[np][2]);
                    MMAFP(acc[mi][2*np+1], Aa[mi], Bb[np][1], Bb[np][3]);
                }
        }
        __syncthreads();
        if (kc + 2 < 8) load_fin(sb + (kc & 1)*FSTG, A0 + (kc+2)*64, W0 + (kc+2)*64, tid);
    }

    const int m0 = bm*128 + wm*64 + (lane >> 2);
    const int n0 = bn*256 + wn*64 + 2*(lane & 3);
    #pragma unroll
    for (int mi = 0; mi < 4; mi++) {
        int m = m0 + mi*16;
        #pragma unroll
        for (int nj = 0; nj < 8; nj++) {
            int n = n0 + nj*8;
            float b0 = bias[n], b1 = bias[n+1];
            float2 v0 = make_float2(acc[mi][nj][0] + b0, acc[mi][nj][1] + b1);
            float2 v1 = make_float2(acc[mi][nj][2] + b0, acc[mi][nj][3] + b1);
            *(float2*)(C + (size_t)m*Vdim + n)     = v0;
            *(float2*)(C + (size_t)(m+8)*Vdim + n) = v1;
        }
    }
}

// ---------------- launch ------------------------------------------------
extern "C" void kernel_launch(void* const* d_in, const int* in_sizes, int n_in,
                              void* d_out, int out_size)
{
    const int*   cas  = (const int*)  d_in[0];
    const int*   tii  = (const int*)  d_in[1];
    const float* emb  = (const float*)d_in[2];
    const float* tlam = (const float*)d_in[3];
    const float* w1   = (const float*)d_in[4];
    const float* b1   = (const float*)d_in[5];
    const float* wh   = (const float*)d_in[6];
    const float* bh   = (const float*)d_in[7];
    const float* wt   = (const float*)d_in[8];
    const float* bt   = (const float*)d_in[9];
    const float* wg   = (const float*)d_in[10];
    const float* bg   = (const float*)d_in[11];
    const float* wm1  = (const float*)d_in[12];
    const float* bm1  = (const float*)d_in[13];
    const float* wti  = (const float*)d_in[14];
    const float* bti  = (const float*)d_in[15];
    const float* wm2  = (const float*)d_in[16];
    const float* bm2  = (const float*)d_in[17];
    const float* wout = (const float*)d_in[18];
    const float* bout = (const float*)d_in[19];
    float* out = (float*)d_out;

    float *p_hidden, *p_map1, *p_ti, *p_enc, *p_bht;
    __nv_bfloat16 *p_emb_h, *p_emb_l, *p_tw_h, *p_tw_l, *p_hid_h, *p_hid_l;
    __nv_bfloat16 *p_dep_h, *p_dep_l, *p_enc_h, *p_enc_l;
    __nv_bfloat16 *p_w1h, *p_w1l, *p_whth, *p_whtl;
    __nv_bfloat16 *p_wm1h, *p_wm1l, *p_wtih, *p_wtil, *p_wgh, *p_wgl;
    __half *p_w16;
    cudaGetSymbolAddress((void**)&p_hidden, g_hidden);
    cudaGetSymbolAddress((void**)&p_map1,   g_map1);
    cudaGetSymbolAddress((void**)&p_ti,     g_ti);
    cudaGetSymbolAddress((void**)&p_enc,    g_enc);
    cudaGetSymbolAddress((void**)&p_bht,    g_bht);
    cudaGetSymbolAddress((void**)&p_emb_h,  g_emb_hi);
    cudaGetSymbolAddress((void**)&p_emb_l,  g_emb_lo);
    cudaGetSymbolAddress((void**)&p_tw_h,   g_tw_hi);
    cudaGetSymbolAddress((void**)&p_tw_l,   g_tw_lo);
    cudaGetSymbolAddress((void**)&p_hid_h,  g_hid_hi);
    cudaGetSymbolAddress((void**)&p_hid_l,  g_hid_lo);
    cudaGetSymbolAddress((void**)&p_dep_h,  g_dep_hi);
    cudaGetSymbolAddress((void**)&p_dep_l,  g_dep_lo);
    cudaGetSymbolAddress((void**)&p_enc_h,  g_enc_hi);
    cudaGetSymbolAddress((void**)&p_enc_l,  g_enc_lo);
    cudaGetSymbolAddress((void**)&p_w1h,    g_w1T_h);
    cudaGetSymbolAddress((void**)&p_w1l,    g_w1T_l);
    cudaGetSymbolAddress((void**)&p_whth,   g_whtT_h);
    cudaGetSymbolAddress((void**)&p_whtl,   g_whtT_l);
    cudaGetSymbolAddress((void**)&p_wm1h,   g_wm1T_h);
    cudaGetSymbolAddress((void**)&p_wm1l,   g_wm1T_l);
    cudaGetSymbolAddress((void**)&p_wtih,   g_wtiT_h);
    cudaGetSymbolAddress((void**)&p_wtil,   g_wtiT_l);
    cudaGetSymbolAddress((void**)&p_wgh,    g_wgT_h);
    cudaGetSymbolAddress((void**)&p_wgl,    g_wgT_l);
    cudaGetSymbolAddress((void**)&p_w16,    g_w16);

    cudaFuncSetAttribute(mgemm_k<1>, cudaFuncAttributeMaxDynamicSharedMemorySize, SMEM_MG);
    cudaFuncSetAttribute(mgemm_k<2>, cudaFuncAttributeMaxDynamicSharedMemorySize, SMEM_MG);
    cudaFuncSetAttribute(mgemm_k<3>, cudaFuncAttributeMaxDynamicSharedMemorySize, SMEM_MG);
    cudaFuncSetAttribute(mgemm_k<5>, cudaFuncAttributeMaxDynamicSharedMemorySize, SMEM_MG);
    cudaFuncSetAttribute(attnmma_k,  cudaFuncAttributeMaxDynamicSharedMemorySize, SMEM_AT);
    cudaFuncSetAttribute(fgemm_k,    cudaFuncAttributeMaxDynamicSharedMemorySize, SMEM_FG);

    caslen_k<<<Bc, 256>>>(cas);
    concatBias_k<<<4, 256>>>(bh, bt);

    // weight preprocessing
    transW_f16_k<<<dim3(Vdim/32, Hdim/32), dim3(32,8)>>>(wout, p_w16);
    transW_bf16_k<<<dim3(16,16), dim3(32,8)>>>(w1,  p_w1h,  p_w1l,  Hdim);
    transW_bf16_k<<<dim3(16,16), dim3(32,8)>>>(wh,  p_whth, p_whtl, Hdim);                    // rows [0,512)
    transW_bf16_k<<<dim3(16,16), dim3(32,8)>>>(wt,  p_whth + Hdim*Hdim, p_whtl + Hdim*Hdim, Hdim); // rows [512,1024)
    transW_bf16_k<<<dim3(16,16), dim3(32,8)>>>(wm1, p_wm1h, p_wm1l, Hdim);
    transW_bf16_k<<<dim3(16,16), dim3(32,8)>>>(wti, p_wtih, p_wtil, Hdim);
    transW_bf16_k<<<dim3(16,32), dim3(32,8)>>>(wg,  p_wgh,  p_wgl,  2*Hdim);

    // activation gathers + splits
    gatherSplit_k<<<(Mrows*Hdim)/256, 256>>>(emb,  cas, p_emb_h, p_emb_l);
    gatherSplit_k<<<(Mrows*Hdim)/256, 256>>>(tlam, tii, p_tw_h,  p_tw_l);

    dim3 gmid(Hdim/MGN, Mrows/MGM);    // (4, 50)
    // hidden = elu(emb@w1+b1)*mask (fp32 + splits)
    mgemm_k<1><<<gmid, 256, SMEM_MG>>>(p_emb_h, p_emb_l, p_emb_h, p_emb_l,
                                       p_w1h, p_w1l, Hdim, 8, b1,
                                       p_hidden, p_hid_h, p_hid_l);
    // hidden^T for attention GEMM2
    transHid_k<<<dim3(7, 16, Bc), dim3(32,8)>>>();
    // head+tail merged: N=1024, grid (8, 50)
    mgemm_k<5><<<dim3(8, Mrows/MGM), 256, SMEM_MG>>>(p_hid_h, p_hid_l, p_hid_h, p_hid_l,
                                       p_whth, p_whtl, Hdim, 8, p_bht,
                                       nullptr, nullptr, nullptr);
    // attention via mma -> depend (fp32 + splits)
    attnmma_k<<<dim3(4, Bc), 256, SMEM_AT>>>();
    // gate -> enc (fp32 + splits)
    mgemm_k<3><<<gmid, 256, SMEM_MG>>>(p_hid_h, p_hid_l, p_dep_h, p_dep_l,
                                       p_wgh, p_wgl, 2*Hdim, 16, bg,
                                       p_enc, p_enc_h, p_enc_l);
    // map1, ti
    mgemm_k<2><<<gmid, 256, SMEM_MG>>>(p_enc_h, p_enc_l, p_enc_h, p_enc_l,
                                       p_wm1h, p_wm1l, Hdim, 8, bm1,
                                       p_map1, nullptr, nullptr);
    mgemm_k<2><<<gmid, 256, SMEM_MG>>>(p_tw_h, p_tw_l, p_tw_h, p_tw_l,
                                       p_wtih, p_wtil, Hdim, 8, bti,
                                       p_ti, nullptr, nullptr);
    // pool -> a16
    pool_k<<<Bc, 256>>>(wm2, bm2);
    // final GEMM 128x256 tiles
    fgemm_k<<<dim3(Vdim/256, Mrows/128), 256, SMEM_FG>>>(bout, out);
}

// round 12
// speedup vs baseline: 1.5099x; 1.5099x over previous
#include <cuda_runtime.h>
#include <cuda_bf16.h>
#include <cuda_fp16.h>
#include <math.h>
#include <stdint.h>

#define Bc   32
#define Ssz  201
#define SL   200
#define Hdim 512
#define Vdim 32000
#define Mrows (Bc*SL)   // 6400

// ---------------- scratch (static device globals; no allocation) ------------
__device__ __align__(16) float g_hidden[Mrows*Hdim];
__device__ __align__(16) float g_depend[Mrows*Hdim];
__device__ __align__(16) float g_enc   [Mrows*Hdim];
__device__ __align__(16) float g_map1  [Mrows*Hdim];
__device__ __align__(16) float g_ti    [Mrows*Hdim];
__device__ int g_caslen[Bc];

// bf16 split activations (hi/lo)
__device__ __align__(16) __nv_bfloat16 g_emb_hi[Mrows*Hdim];
__device__ __align__(16) __nv_bfloat16 g_emb_lo[Mrows*Hdim];
__device__ __align__(16) __nv_bfloat16 g_tw_hi [Mrows*Hdim];
__device__ __align__(16) __nv_bfloat16 g_tw_lo [Mrows*Hdim];
__device__ __align__(16) __nv_bfloat16 g_hid_hi[Mrows*Hdim];
__device__ __align__(16) __nv_bfloat16 g_hid_lo[Mrows*Hdim];
__device__ __align__(16) __nv_bfloat16 g_hed_hi[Mrows*Hdim];
__device__ __align__(16) __nv_bfloat16 g_hed_lo[Mrows*Hdim];
__device__ __align__(16) __nv_bfloat16 g_tal_hi[Mrows*Hdim];
__device__ __align__(16) __nv_bfloat16 g_tal_lo[Mrows*Hdim];
__device__ __align__(16) __nv_bfloat16 g_dep_hi[Mrows*Hdim];
__device__ __align__(16) __nv_bfloat16 g_dep_lo[Mrows*Hdim];
__device__ __align__(16) __nv_bfloat16 g_enc_hi[Mrows*Hdim];
__device__ __align__(16) __nv_bfloat16 g_enc_lo[Mrows*Hdim];

// hidden transposed per batch: [b][h][jpad=256] (zero-init covers pad)
__device__ __align__(16) __nv_bfloat16 g_hidT_h[Bc*Hdim*256];
__device__ __align__(16) __nv_bfloat16 g_hidT_l[Bc*Hdim*256];

// bf16 split transposed weights [N, K] K-major
__device__ __align__(16) __nv_bfloat16 g_w1T_h [Hdim*Hdim];
__device__ __align__(16) __nv_bfloat16 g_w1T_l [Hdim*Hdim];
__device__ __align__(16) __nv_bfloat16 g_whtT_h[2*Hdim*Hdim];  // [1024, 512] wh|wt stacked
__device__ __align__(16) __nv_bfloat16 g_whtT_l[2*Hdim*Hdim];
__device__ __align__(16) __nv_bfloat16 g_wm1T_h[Hdim*Hdim];
__device__ __align__(16) __nv_bfloat16 g_wm1T_l[Hdim*Hdim];
__device__ __align__(16) __nv_bfloat16 g_wtiT_h[Hdim*Hdim];
__device__ __align__(16) __nv_bfloat16 g_wtiT_l[Hdim*Hdim];
__device__ __align__(16) __nv_bfloat16 g_wgT_h [Hdim*2*Hdim];
__device__ __align__(16) __nv_bfloat16 g_wgT_l [Hdim*2*Hdim];
__device__ __align__(16) float g_bht[2*Hdim];   // bh|bt stacked

// fp16 operands for the final 1-term GEMM
__device__ __align__(16) __half g_a16[Mrows*Hdim];
__device__ __align__(16) __half g_w16[(size_t)Vdim*Hdim];   // [V, H] K-major

__device__ __forceinline__ float elu_f(float x){ return x > 0.f ? x : (expf(x) - 1.f); }

// ========================= mma helpers =====================================
__device__ __forceinline__ uint32_t smem_u32(const void* p){
    uint32_t a;
    asm("{ .reg .u64 t; cvta.to.shared.u64 t, %1; cvt.u32.u64 %0, t; }" : "=r"(a) : "l"(p));
    return a;
}
#define SWZ128(off) ((off) ^ (((off) >> 3) & 0x70))

__device__ __forceinline__ void cpa16(uint32_t s, const void* g){
    asm volatile("cp.async.cg.shared.global [%0], [%1], 16;" :: "r"(s), "l"(g));
}

#define LDSM4(r0, r1, r2, r3, addr) \
    asm volatile("ldmatrix.sync.aligned.m8n8.x4.shared.b16 {%0,%1,%2,%3}, [%4];" \
        : "=r"(r0), "=r"(r1), "=r"(r2), "=r"(r3) : "r"(addr))

#define MMABF(c, a, b0, b1) \
    asm volatile("mma.sync.aligned.m16n8k16.row.col.f32.bf16.bf16.f32 " \
        "{%0,%1,%2,%3},{%4,%5,%6,%7},{%8,%9},{%0,%1,%2,%3};" \
        : "+f"((c)[0]), "+f"((c)[1]), "+f"((c)[2]), "+f"((c)[3]) \
        : "r"((a)[0]), "r"((a)[1]), "r"((a)[2]), "r"((a)[3]), "r"(b0), "r"(b1))

#define MMAFP(c, a, b0, b1) \
    asm volatile("mma.sync.aligned.m16n8k16.row.col.f32.f16.f16.f32 " \
        "{%0,%1,%2,%3},{%4,%5,%6,%7},{%8,%9},{%0,%1,%2,%3};" \
        : "+f"((c)[0]), "+f"((c)[1]), "+f"((c)[2]), "+f"((c)[3]) \
        : "r"((a)[0]), "r"((a)[1]), "r"((a)[2]), "r"((a)[3]), "r"(b0), "r"(b1))

// ---------------- cas_len -----------------------------------------------
__global__ void caslen_k(const int* __restrict__ cas){
    int b = blockIdx.x, tid = threadIdx.x;
    int c = (tid < SL && cas[b*Ssz + tid] != 0) ? 1 : 0;
    for (int o = 16; o; o >>= 1) c += __shfl_xor_sync(0xffffffffu, c, o);
    __shared__ int s[8];
    if ((tid & 31) == 0) s[tid >> 5] = c;
    __syncthreads();
    if (tid == 0) { int t = 0; for (int q = 0; q < 8; q++) t += s[q]; g_caslen[b] = t; }
}

__global__ void concatBias_k(const float* __restrict__ bh, const float* __restrict__ bt){
    int i = threadIdx.x + blockIdx.x*256;
    g_bht[i] = (i < Hdim) ? bh[i] : bt[i - Hdim];
}

// ---------------- weight transpose + split -------------------------------
__global__ void transW_bf16_k(const float* __restrict__ w,
                              __nv_bfloat16* __restrict__ hi,
                              __nv_bfloat16* __restrict__ lo, int Kdim){
    __shared__ float t[32][33];
    int n0 = blockIdx.x*32, k0 = blockIdx.y*32;
    int x = threadIdx.x, y = threadIdx.y;
    for (int i = y; i < 32; i += 8)
        t[i][x] = w[(size_t)(k0+i)*Hdim + n0 + x];
    __syncthreads();
    for (int nn = y; nn < 32; nn += 8) {
        float v = t[x][nn];
        __nv_bfloat16 h = __float2bfloat16(v);
        size_t o = (size_t)(n0+nn)*Kdim + k0 + x;
        hi[o] = h;
        lo[o] = __float2bfloat16(v - __bfloat162float(h));
    }
}

__global__ void transW_f16_k(const float* __restrict__ w, __half* __restrict__ out){
    __shared__ float t[32][33];
    int n0 = blockIdx.x*32, k0 = blockIdx.y*32;
    int x = threadIdx.x, y = threadIdx.y;
    for (int i = y; i < 32; i += 8)
        t[i][x] = w[(size_t)(k0+i)*Vdim + n0 + x];
    __syncthreads();
    for (int nn = y; nn < 32; nn += 8)
        out[(size_t)(n0+nn)*Hdim + k0 + x] = __float2half(t[x][nn]);
}

__global__ void gatherSplit_k(const float* __restrict__ table, const int* __restrict__ idx,
                              __nv_bfloat16* __restrict__ hi, __nv_bfloat16* __restrict__ lo){
    int i = blockIdx.x*256 + threadIdx.x;
    int r = i >> 9, c = i & 511;
    int row = idx[(r/SL)*Ssz + (r%SL)];
    float v = table[(size_t)row*Hdim + c];
    __nv_bfloat16 h = __float2bfloat16(v);
    hi[i] = h;
    lo[i] = __float2bfloat16(v - __bfloat162float(h));
}

// hidden [b*SL+j][h] -> hidT hi/lo [b][h][256]
__global__ void transHid_k(){
    __shared__ float t[32][33];
    int b = blockIdx.z;
    int j0 = blockIdx.x*32, h0 = blockIdx.y*32;
    int x = threadIdx.x, y = threadIdx.y;
    for (int i = y; i < 32; i += 8) {
        int j = j0 + i;
        t[i][x] = (j < SL) ? g_hidden[(size_t)(b*SL + j)*Hdim + h0 + x] : 0.f;
    }
    __syncthreads();
    for (int hh = y; hh < 32; hh += 8) {
        float v = t[x][hh];
        __nv_bfloat16 h = __float2bfloat16(v);
        size_t o = ((size_t)(b*Hdim + h0 + hh))*256 + j0 + x;
        g_hidT_h[o] = h;
        g_hidT_l[o] = __float2bfloat16(v - __bfloat162float(h));
    }
}

// ---------------- mid bf16 3-term mma GEMM (double-buffered, R9 config) --
#define MGM 128
#define MGN 128
#define MKC 64
#define MOFF_AH 0
#define MOFF_AL 16384
#define MOFF_BH 32768
#define MOFF_BL 49152
#define MSTG 65536
#define SMEM_MG (2*MSTG)   // 131072

// EPI: 1 bias+elu+mask+splits; 2 bias+elu; 3 gate-combine+mask+splits;
//      5 bias+splits into head(c<512)/tail(c>=512)
template<int EPI>
__device__ __forceinline__ void epi_store(float v, int r, int c,
    const float* __restrict__ bias, float* __restrict__ C,
    __nv_bfloat16* __restrict__ Chi, __nv_bfloat16* __restrict__ Clo)
{
    v += bias[c];
    if (EPI == 1 || EPI == 2) v = elu_f(v);
    if (EPI == 3) {
        float g = 1.f / (1.f + expf(-v));
        float h = g_hidden[(size_t)r*Hdim + c];
        float d = g_depend[(size_t)r*Hdim + c];
        v = g*h + (1.f - g)*d;
    }
    if (EPI == 1 || EPI == 3) {
        int bb = r / SL, ii = r % SL;
        if (ii >= g_caslen[bb]) v = 0.f;
    }
    if (EPI == 5) {
        __nv_bfloat16 h = __float2bfloat16(v);
        __nv_bfloat16 l = __float2bfloat16(v - __bfloat162float(h));
        if (c < Hdim) {
            g_hed_hi[(size_t)r*Hdim + c] = h;
            g_hed_lo[(size_t)r*Hdim + c] = l;
        } else {
            g_tal_hi[(size_t)r*Hdim + c - Hdim] = h;
            g_tal_lo[(size_t)r*Hdim + c - Hdim] = l;
        }
        return;
    }
    C[(size_t)r*Hdim + c] = v;
    if (EPI == 1 || EPI == 3) {
        __nv_bfloat16 h = __float2bfloat16(v);
        Chi[(size_t)r*Hdim + c] = h;
        Clo[(size_t)r*Hdim + c] = __float2bfloat16(v - __bfloat162float(h));
    }
}

template<int EPI>
__global__ __launch_bounds__(256) void mgemm_k(
    const __nv_bfloat16* __restrict__ Ah0, const __nv_bfloat16* __restrict__ Al0,
    const __nv_bfloat16* __restrict__ Ah1, const __nv_bfloat16* __restrict__ Al1,
    const __nv_bfloat16* __restrict__ Wh,  const __nv_bfloat16* __restrict__ Wl,
    int ldw, int nkc,
    const float* __restrict__ bias, float* __restrict__ C,
    __nv_bfloat16* __restrict__ Chi, __nv_bfloat16* __restrict__ Clo)
{
    extern __shared__ char smem[];
    const int tid = threadIdx.x, lane = tid & 31, wid = tid >> 5;
    const int bn = blockIdx.x, bm = blockIdx.y;
    const int wm = wid & 1, wn = wid >> 1;
    const int rl = lane & 15, gl = lane >> 4;
    uint32_t sb = smem_u32(smem);

    float acc[4][4][4];
    #pragma unroll
    for (int mi = 0; mi < 4; mi++)
        #pragma unroll
        for (int ni = 0; ni < 4; ni++)
            #pragma unroll
            for (int q = 0; q < 4; q++) acc[mi][ni][q] = 0.f;

    auto load_stage = [&](int kc, int buf){
        const __nv_bfloat16 *ah, *al; int koff;
        if (kc < 8) { ah = Ah0; al = Al0; koff = kc*MKC; }
        else        { ah = Ah1; al = Al1; koff = (kc-8)*MKC; }
        const __nv_bfloat16* ap_h = ah + (size_t)(bm*MGM)*Hdim + koff;
        const __nv_bfloat16* ap_l = al + (size_t)(bm*MGM)*Hdim + koff;
        const __nv_bfloat16* wp_h = Wh + (size_t)(bn*MGN)*ldw + kc*MKC;
        const __nv_bfloat16* wp_l = Wl + (size_t)(bn*MGN)*ldw + kc*MKC;
        uint32_t base = sb + buf*MSTG;
        #pragma unroll
        for (int t = 0; t < 4; t++) {
            int G = tid + t*256; int r = G >> 3, g = G & 7;
            uint32_t d = SWZ128((uint32_t)(r*128 + g*16));
            cpa16(base + MOFF_AH + d, ap_h + (size_t)r*Hdim + g*8);
            cpa16(base + MOFF_AL + d, ap_l + (size_t)r*Hdim + g*8);
            cpa16(base + MOFF_BH + d, wp_h + (size_t)r*ldw + g*8);
            cpa16(base + MOFF_BL + d, wp_l + (size_t)r*ldw + g*8);
        }
        asm volatile("cp.async.commit_group;" ::: "memory");
    };

    load_stage(0, 0);
    load_stage(1, 1);

    for (int kc = 0; kc < nkc; kc++) {
        if (kc < nkc-1) asm volatile("cp.async.wait_group 1;" ::: "memory");
        else            asm volatile("cp.async.wait_group 0;" ::: "memory");
        __syncthreads();
        const uint32_t base = sb + (kc & 1)*MSTG;
        #pragma unroll
        for (int ks = 0; ks < 4; ks++) {
            const int kg = 2*ks + gl;
            uint32_t Aa[4][4], Bb[2][4], Al2[4][4];
            #pragma unroll
            for (int mi = 0; mi < 4; mi++) {
                uint32_t ad = base + MOFF_AH + SWZ128((uint32_t)((wm*64 + mi*16 + rl)*128 + kg*16));
                LDSM4(Aa[mi][0], Aa[mi][1], Aa[mi][2], Aa[mi][3], ad);
            }
            #pragma unroll
            for (int np = 0; np < 2; np++) {
                uint32_t bd = base + MOFF_BH + SWZ128((uint32_t)((wn*32 + np*16 + rl)*128 + kg*16));
                LDSM4(Bb[np][0], Bb[np][1], Bb[np][2], Bb[np][3], bd);
            }
            #pragma unroll
            for (int mi = 0; mi < 4; mi++)
                #pragma unroll
                for (int np = 0; np < 2; np++) {
                    MMABF(acc[mi][2*np  ], Aa[mi], Bb[np][0], Bb[np][2]);
                    MMABF(acc[mi][2*np+1], Aa[mi], Bb[np][1], Bb[np][3]);
                }
            #pragma unroll
            for (int mi = 0; mi < 4; mi++) {
                uint32_t ad = base + MOFF_AL + SWZ128((uint32_t)((wm*64 + mi*16 + rl)*128 + kg*16));
                LDSM4(Al2[mi][0], Al2[mi][1], Al2[mi][2], Al2[mi][3], ad);
            }
            #pragma unroll
            for (int mi = 0; mi < 4; mi++)
                #pragma unroll
                for (int np = 0; np < 2; np++) {
                    MMABF(acc[mi][2*np  ], Al2[mi], Bb[np][0], Bb[np][2]);
                    MMABF(acc[mi][2*np+1], Al2[mi], Bb[np][1], Bb[np][3]);
                }
            #pragma unroll
            for (int np = 0; np < 2; np++) {
                uint32_t bd = base + MOFF_BL + SWZ128((uint32_t)((wn*32 + np*16 + rl)*128 + kg*16));
                LDSM4(Bb[np][0], Bb[np][1], Bb[np][2], Bb[np][3], bd);
            }
            #pragma unroll
            for (int mi = 0; mi < 4; mi++)
                #pragma unroll
                for (int np = 0; np < 2; np++) {
                    MMABF(acc[mi][2*np  ], Aa[mi], Bb[np][0], Bb[np][2]);
                    MMABF(acc[mi][2*np+1], Aa[mi], Bb[np][1], Bb[np][3]);
                }
        }
        __syncthreads();
        if (kc + 2 < nkc) load_stage(kc + 2, kc & 1);
    }

    const int mbase = bm*MGM + wm*64 + (lane >> 2);
    const int nbase = bn*MGN + wn*32 + 2*(lane & 3);
    #pragma unroll
    for (int mi = 0; mi < 4; mi++) {
        int r0 = mbase + mi*16, r1 = r0 + 8;
        #pragma unroll
        for (int ni = 0; ni < 4; ni++) {
            int n = nbase + ni*8;
            epi_store<EPI>(acc[mi][ni][0], r0, n,   bias, C, Chi, Clo);
            epi_store<EPI>(acc[mi][ni][1], r0, n+1, bias, C, Chi, Clo);
            epi_store<EPI>(acc[mi][ni][2], r1, n,   bias, C, Chi, Clo);
            epi_store<EPI>(acc[mi][ni][3], r1, n+1, bias, C, Chi, Clo);
        }
    }
}

// ---------------- attention via mma --------------------------------------
#define AT_S_HI 0
#define AT_S_LO 32768
#define AT_STG  65536
#define AT_RED  (AT_STG + 131072)
#define SMEM_AT (196608 + 2048)

__global__ __launch_bounds__(256) void attnmma_k()
{
    extern __shared__ char smem[];
    const int tid = threadIdx.x, lane = tid & 31, wid = tid >> 5;
    const int t = blockIdx.x, b = blockIdx.y;
    const int len = g_caslen[b];
    const int rl = lane & 15, gl = lane >> 4;
    uint32_t sb = smem_u32(smem);
    const uint32_t stg = sb + AT_STG;
    float* red = (float*)(smem + AT_RED);

    float acc1[4][4][4];
    #pragma unroll
    for (int mi = 0; mi < 4; mi++)
        #pragma unroll
        for (int ni = 0; ni < 4; ni++)
            #pragma unroll
            for (int q = 0; q < 4; q++) acc1[mi][ni][q] = 0.f;

    for (int kc = 0; kc < 8; kc++) {
        #pragma unroll
        for (int q = 0; q < 2; q++) {
            int G = tid + q*256; int r = G >> 3, g = G & 7;
            int gi = t*64 + r; if (gi >= SL) gi = SL-1;
            size_t go = (size_t)(b*SL + gi)*Hdim + kc*64 + g*8;
            uint32_t d = SWZ128((uint32_t)(r*128 + g*16));
            cpa16(stg + 0    + d, g_hed_hi + go);
            cpa16(stg + 8192 + d, g_hed_lo + go);
        }
        #pragma unroll
        for (int q = 0; q < 8; q++) {
            int G = tid + q*256; int r = G >> 3, g = G & 7;
            int gj = (r < SL) ? r : SL-1;
            size_t go = (size_t)(b*SL + gj)*Hdim + kc*64 + g*8;
            uint32_t d = SWZ128((uint32_t)(r*128 + g*16));
            cpa16(stg + 16384 + d, g_tal_hi + go);
            cpa16(stg + 49152 + d, g_tal_lo + go);
        }
        asm volatile("cp.async.commit_group;" ::: "memory");
        asm volatile("cp.async.wait_group 0;" ::: "memory");
        __syncthreads();

        #pragma unroll
        for (int ks = 0; ks < 4; ks++) {
            const int kg = 2*ks + gl;
            uint32_t Aa[4][4], Bb[2][4], Al2[4][4];
            #pragma unroll
            for (int mi = 0; mi < 4; mi++) {
                uint32_t ad = stg + 0 + SWZ128((uint32_t)((mi*16 + rl)*128 + kg*16));
                LDSM4(Aa[mi][0], Aa[mi][1], Aa[mi][2], Aa[mi][3], ad);
            }
            #pragma unroll
            for (int np = 0; np < 2; np++) {
                uint32_t bd = stg + 16384 + SWZ128((uint32_t)((wid*32 + np*16 + rl)*128 + kg*16));
                LDSM4(Bb[np][0], Bb[np][1], Bb[np][2], Bb[np][3], bd);
            }
            #pragma unroll
            for (int mi = 0; mi < 4; mi++)
                #pragma unroll
                for (int np = 0; np < 2; np++) {
                    MMABF(acc1[mi][2*np  ], Aa[mi], Bb[np][0], Bb[np][2]);
                    MMABF(acc1[mi][2*np+1], Aa[mi], Bb[np][1], Bb[np][3]);
                }
            #pragma unroll
            for (int mi = 0; mi < 4; mi++) {
                uint32_t ad = stg + 8192 + SWZ128((uint32_t)((mi*16 + rl)*128 + kg*16));
                LDSM4(Al2[mi][0], Al2[mi][1], Al2[mi][2], Al2[mi][3], ad);
            }
            #pragma unroll
            for (int mi = 0; mi < 4; mi++)
                #pragma unroll
                for (int np = 0; np < 2; np++) {
                    MMABF(acc1[mi][2*np  ], Al2[mi], Bb[np][0], Bb[np][2]);
                    MMABF(acc1[mi][2*np+1], Al2[mi], Bb[np][1], Bb[np][3]);
                }
            #pragma unroll
            for (int np = 0; np < 2; np++) {
                uint32_t bd = stg + 49152 + SWZ128((uint32_t)((wid*32 + np*16 + rl)*128 + kg*16));
                LDSM4(Bb[np][0], Bb[np][1], Bb[np][2], Bb[np][3], bd);
            }
            #pragma unroll
            for (int mi = 0; mi < 4; mi++)
                #pragma unroll
                for (int np = 0; np < 2; np++) {
                    MMABF(acc1[mi][2*np  ], Aa[mi], Bb[np][0], Bb[np][2]);
                    MMABF(acc1[mi][2*np+1], Aa[mi], Bb[np][1], Bb[np][3]);
                }
        }
        __syncthreads();
    }

    const int rbase = lane >> 2, cbase = 2*(lane & 3);
    float rmax[4][2];
    #pragma unroll
    for (int mi = 0; mi < 4; mi++)
        #pragma unroll
        for (int qh = 0; qh < 2; qh++) {
            int ig = t*64 + mi*16 + rbase + 8*qh;
            float m = -1e30f;
            #pragma unroll
            for (int ni = 0; ni < 4; ni++)
                #pragma unroll
                for (int q0 = 0; q0 < 2; q0++) {
                    int jg = wid*32 + ni*8 + cbase + q0;
                    float v = acc1[mi][ni][qh*2 + q0];
                    if (jg < ig && jg < len) m = fmaxf(m, v);
                }
            m = fmaxf(m, __shfl_xor_sync(0xffffffffu, m, 1));
            m = fmaxf(m, __shfl_xor_sync(0xffffffffu, m, 2));
            rmax[mi][qh] = m;
            if ((lane & 3) == 0) red[(mi*16 + rbase + 8*qh)*8 + wid] = m;
        }
    __syncthreads();
    #pragma unroll
    for (int mi = 0; mi < 4; mi++)
        #pragma unroll
        for (int qh = 0; qh < 2; qh++) {
            float m = -1e30f;
            int row = mi*16 + rbase + 8*qh;
            #pragma unroll
            for (int w = 0; w < 8; w++) m = fmaxf(m, red[row*8 + w]);
            rmax[mi][qh] = m;
        }
    __syncthreads();

    float rsum[4][2];
    #pragma unroll
    for (int mi = 0; mi < 4; mi++)
        #pragma unroll
        for (int qh = 0; qh < 2; qh++) {
            int ig = t*64 + mi*16 + rbase + 8*qh;
            float s = 0.f;
            #pragma unroll
            for (int ni = 0; ni < 4; ni++)
                #pragma unroll
                for (int q0 = 0; q0 < 2; q0++) {
                    int jg = wid*32 + ni*8 + cbase + q0;
                    float v = acc1[mi][ni][qh*2 + q0];
                    float e = (jg < ig && jg < len) ? expf(v - rmax[mi][qh]) : 0.f;
                    acc1[mi][ni][qh*2 + q0] = e;
                    s += e;
                }
            s += __shfl_xor_sync(0xffffffffu, s, 1);
            s += __shfl_xor_sync(0xffffffffu, s, 2);
            if ((lane & 3) == 0) red[(mi*16 + rbase + 8*qh)*8 + wid] = s;
        }
    __syncthreads();
    #pragma unroll
    for (int mi = 0; mi < 4; mi++)
        #pragma unroll
        for (int qh = 0; qh < 2; qh++) {
            float s = 0.f;
            int row = mi*16 + rbase + 8*qh;
            #pragma unroll
            for (int w = 0; w < 8; w++) s += red[row*8 + w];
            rsum[mi][qh] = (s > 0.f) ? 1.f/s : 0.f;
        }

    #pragma unroll
    for (int mi = 0; mi < 4; mi++)
        #pragma unroll
        for (int qh = 0; qh < 2; qh++) {
            int row = mi*16 + rbase + 8*qh;
            #pragma unroll
            for (int ni = 0; ni < 4; ni++)
                #pragma unroll
                for (int q0 = 0; q0 < 2; q0++) {
                    int jg = wid*32 + ni*8 + cbase + q0;
                    float p = acc1[mi][ni][qh*2 + q0] * rsum[mi][qh];
                    __nv_bfloat16 ph = __float2bfloat16(p);
                    __nv_bfloat16 pl = __float2bfloat16(p - __bfloat162float(ph));
                    int chunk = jg >> 6, col = jg & 63;
                    uint32_t off = chunk*8192 + SWZ128((uint32_t)(row*128 + col*2));
                    uint16_t uh = *(uint16_t*)&ph, ul = *(uint16_t*)&pl;
                    asm volatile("st.shared.b16 [%0], %1;" :: "r"(sb + AT_S_HI + off), "h"(uh));
                    asm volatile("st.shared.b16 [%0], %1;" :: "r"(sb + AT_S_LO + off), "h"(ul));
                }
        }
    __syncthreads();

    float acc2[4][8][4];
    #pragma unroll
    for (int mi = 0; mi < 4; mi++)
        #pragma unroll
        for (int nj = 0; nj < 8; nj++)
            #pragma unroll
            for (int q = 0; q < 4; q++) acc2[mi][nj][q] = 0.f;

    for (int kc = 0; kc < 4; kc++) {
        #pragma unroll
        for (int q = 0; q < 16; q++) {
            int G = tid + q*256; int r = G >> 3, g = G & 7;
            size_t go = ((size_t)(b*Hdim + r))*256 + kc*64 + g*8;
            uint32_t d = SWZ128((uint32_t)(r*128 + g*16));
            cpa16(stg + 0     + d, g_hidT_h + go);
            cpa16(stg + 65536 + d, g_hidT_l + go);
        }
        asm volatile("cp.async.commit_group;" ::: "memory");
        asm volatile("cp.async.wait_group 0;" ::: "memory");
        __syncthreads();

        #pragma unroll
        for (int ks = 0; ks < 4; ks++) {
            const int kg = 2*ks + gl;
            uint32_t Aa[4][4], Bb[4][4], Al2[4][4];
            #pragma unroll
            for (int mi = 0; mi < 4; mi++) {
                uint32_t ad = sb + AT_S_HI + kc*8192 + SWZ128((uint32_t)((mi*16 + rl)*128 + kg*16));
                LDSM4(Aa[mi][0], Aa[mi][1], Aa[mi][2], Aa[mi][3], ad);
            }
            #pragma unroll
            for (int np = 0; np < 4; np++) {
                uint32_t bd = stg + 0 + SWZ128((uint32_t)((wid*64 + np*16 + rl)*128 + kg*16));
                LDSM4(Bb[np][0], Bb[np][1], Bb[np][2], Bb[np][3], bd);
            }
            #pragma unroll
            for (int mi = 0; mi < 4; mi++)
                #pragma unroll
                for (int np = 0; np < 4; np++) {
                    MMABF(acc2[mi][2*np  ], Aa[mi], Bb[np][0], Bb[np][2]);
                    MMABF(acc2[mi][2*np+1], Aa[mi], Bb[np][1], Bb[np][3]);
                }
            #pragma unroll
            for (int mi = 0; mi < 4; mi++) {
                uint32_t ad = sb + AT_S_LO + kc*8192 + SWZ128((uint32_t)((mi*16 + rl)*128 + kg*16));
                LDSM4(Al2[mi][0], Al2[mi][1], Al2[mi][2], Al2[mi][3], ad);
            }
            #pragma unroll
            for (int mi = 0; mi < 4; mi++)
                #pragma unroll
                for (int np = 0; np < 4; np++) {
                    MMABF(acc2[mi][2*np  ], Al2[mi], Bb[np][0], Bb[np][2]);
                    MMABF(acc2[mi][2*np+1], Al2[mi], Bb[np][1], Bb[np][3]);
                }
            #pragma unroll
            for (int np = 0; np < 4; np++) {
                uint32_t bd = stg + 65536 + SWZ128((uint32_t)((wid*64 + np*16 + rl)*128 + kg*16));
                LDSM4(Bb[np][0], Bb[np][1], Bb[np][2], Bb[np][3], bd);
            }
            #pragma unroll
            for (int mi = 0; mi < 4; mi++)
                #pragma unroll
                for (int np = 0; np < 4; np++) {
                    MMABF(acc2[mi][2*np  ], Aa[mi], Bb[np][0], Bb[np][2]);
                    MMABF(acc2[mi][2*np+1], Aa[mi], Bb[np][1], Bb[np][3]);
                }
        }
        __syncthreads();
    }

    #pragma unroll
    for (int mi = 0; mi < 4; mi++)
        #pragma unroll
        for (int qh = 0; qh < 2; qh++) {
            int ig = t*64 + mi*16 + rbase + 8*qh;
            if (ig >= SL) continue;
            size_t rowo = (size_t)(b*SL + ig)*Hdim;
            #pragma unroll
            for (int nj = 0; nj < 8; nj++)
                #pragma unroll
                for (int q0 = 0; q0 < 2; q0++) {
                    int h = wid*64 + nj*8 + cbase + q0;
                    float v = acc2[mi][nj][qh*2 + q0];
                    g_depend[rowo + h] = v;
                    __nv_bfloat16 vh = __float2bfloat16(v);
                    g_dep_hi[rowo + h] = vh;
                    g_dep_lo[rowo + h] = __float2bfloat16(v - __bfloat162float(vh));
                }
        }
}

// ---------------- pool ---------------------------------------------------
__global__ __launch_bounds__(256) void pool_k(
    const float* __restrict__ wm2, const float* __restrict__ bm2)
{
    int b = blockIdx.x, tid = threadIdx.x, w = tid >> 5, l = tid & 31;
    __shared__ float m2[SL];
    __shared__ float red[8];
    int len = g_caslen[b];

    for (int i = w; i < SL; i += 8) {
        size_t r = (size_t)b*SL + i;
        float s = 0.f;
        #pragma unroll 4
        for (int h = l; h < Hdim; h += 32)
            s = fmaf(g_map1[r*Hdim + h] * g_ti[r*Hdim + h], wm2[h], s);
        for (int o = 16; o; o >>= 1) s += __shfl_xor_sync(0xffffffffu, s, o);
        if (l == 0) m2[i] = s + bm2[0];
    }
    __syncthreads();

    float mx = -1e30f;
    for (int i = tid; i < len; i += 256) mx = fmaxf(mx, m2[i]);
    for (int o = 16; o; o >>= 1) mx = fmaxf(mx, __shfl_xor_sync(0xffffffffu, mx, o));
    if (l == 0) red[w] = mx;
    __syncthreads();
    if (tid == 0) { float mm = red[0]; for (int q = 1; q < 8; q++) mm = fmaxf(mm, red[q]); red[0] = mm; }
    __syncthreads();
    mx = red[0];

    float sum = 0.f;
    for (int i = tid; i < len; i += 256) { float e = expf(m2[i] - mx); m2[i] = e; sum += e; }
    for (int o = 16; o; o >>= 1) sum += __shfl_xor_sync(0xffffffffu, sum, o);
    __syncthreads();
    if (l == 0) red[w] = sum;
    __syncthreads();
    if (tid == 0) { float t = 0.f; for (int q = 0; q < 8; q++) t += red[q]; red[0] = t; }
    __syncthreads();
    float inv = (len > 0) ? 1.f / red[0] : 0.f;

    for (int i = tid; i < SL; i += 256) m2[i] = (i < len) ? m2[i]*inv : 0.f;
    __syncthreads();

    size_t base = (size_t)b*SL*Hdim;
    for (int e = tid; e < SL*Hdim; e += 256) {
        int i = e >> 9;
        g_a16[base + e] = __float2half(m2[i] * g_enc[base + e]);
    }
}

// ---------------- final fp16 GEMM: tile 128x128, 2 CTAs/SM (R9 config) ---
#define FSTG 32768
#define SMEM_FG (2*FSTG)   // 65536

__device__ __forceinline__ void load_fin(uint32_t base, const __half* A, const __half* W, int tid){
    #pragma unroll
    for (int t = 0; t < 4; t++) {
        int G = tid + t*256; int r = G >> 3, g = G & 7;
        uint32_t d = SWZ128((uint32_t)(r*128 + g*16));
        cpa16(base + d,         A + (size_t)r*Hdim + g*8);
        cpa16(base + 16384 + d, W + (size_t)r*Hdim + g*8);
    }
    asm volatile("cp.async.commit_group;" ::: "memory");
}

__global__ __launch_bounds__(256, 2) void fgemm_k(
    const float* __restrict__ bias, float* __restrict__ C)
{
    extern __shared__ char smem[];
    const int tid = threadIdx.x, lane = tid & 31, wid = tid >> 5;
    const int bn = blockIdx.x, bm = blockIdx.y;
    const int wm = wid & 1, wn = wid >> 1;
    const int rl = lane & 15, gl = lane >> 4;
    uint32_t sb = smem_u32(smem);

    float acc[4][4][4];
    #pragma unroll
    for (int mi = 0; mi < 4; mi++)
        #pragma unroll
        for (int ni = 0; ni < 4; ni++)
            #pragma unroll
            for (int q = 0; q < 4; q++) acc[mi][ni][q] = 0.f;

    const __half* A0 = g_a16 + (size_t)(bm*128)*Hdim;
    const __half* W0 = g_w16 + (size_t)(bn*128)*Hdim;

    load_fin(sb,        A0,      W0,      tid);
    load_fin(sb + FSTG, A0 + 64, W0 + 64, tid);

    for (int kc = 0; kc < 8; kc++) {
        if (kc < 7) asm volatile("cp.async.wait_group 1;" ::: "memory");
        else        asm volatile("cp.async.wait_group 0;" ::: "memory");
        __syncthreads();
        const uint32_t base = sb + (kc & 1)*FSTG;
        #pragma unroll
        for (int ks = 0; ks < 4; ks++) {
            const int kg = 2*ks + gl;
            uint32_t Aa[4][4], Bb[2][4];
            #pragma unroll
            for (int mi = 0; mi < 4; mi++) {
                uint32_t ad = base + SWZ128((uint32_t)((wm*64 + mi*16 + rl)*128 + kg*16));
                LDSM4(Aa[mi][0], Aa[mi][1], Aa[mi][2], Aa[mi][3], ad);
            }
            #pragma unroll
            for (int np = 0; np < 2; np++) {
                uint32_t bd = base + 16384 + SWZ128((uint32_t)((wn*32 + np*16 + rl)*128 + kg*16));
                LDSM4(Bb[np][0], Bb[np][1], Bb[np][2], Bb[np][3], bd);
            }
            #pragma unroll
            for (int mi = 0; mi < 4; mi++)
                #pragma unroll
                for (int np = 0; np < 2; np++) {
                    MMAFP(acc[mi][2*np  ], Aa[mi], Bb[np][0], Bb[np][2]);
                    MMAFP(acc[mi][2*np+1], Aa[mi], Bb[np][1], Bb[np][3]);
                }
        }
        __syncthreads();
        if (kc + 2 < 8) load_fin(sb + (kc & 1)*FSTG, A0 + (kc+2)*64, W0 + (kc+2)*64, tid);
    }

    const int m0 = bm*128 + wm*64 + (lane >> 2);
    const int n0 = bn*128 + wn*32 + 2*(lane & 3);
    #pragma unroll
    for (int mi = 0; mi < 4; mi++) {
        int m = m0 + mi*16;
        #pragma unroll
        for (int ni = 0; ni < 4; ni++) {
            int n = n0 + ni*8;
            float b0 = bias[n], b1 = bias[n+1];
            float2 v0 = make_float2(acc[mi][ni][0] + b0, acc[mi][ni][1] + b1);
            float2 v1 = make_float2(acc[mi][ni][2] + b0, acc[mi][ni][3] + b1);
            *(float2*)(C + (size_t)m*Vdim + n)     = v0;
            *(float2*)(C + (size_t)(m+8)*Vdim + n) = v1;
        }
    }
}

// ---------------- launch ------------------------------------------------
extern "C" void kernel_launch(void* const* d_in, const int* in_sizes, int n_in,
                              void* d_out, int out_size)
{
    const int*   cas  = (const int*)  d_in[0];
    const int*   tii  = (const int*)  d_in[1];
    const float* emb  = (const float*)d_in[2];
    const float* tlam = (const float*)d_in[3];
    const float* w1   = (const float*)d_in[4];
    const float* b1   = (const float*)d_in[5];
    const float* wh   = (const float*)d_in[6];
    const float* bh   = (const float*)d_in[7];
    const float* wt   = (const float*)d_in[8];
    const float* bt   = (const float*)d_in[9];
    const float* wg   = (const float*)d_in[10];
    const float* bg   = (const float*)d_in[11];
    const float* wm1  = (const float*)d_in[12];
    const float* bm1  = (const float*)d_in[13];
    const float* wti  = (const float*)d_in[14];
    const float* bti  = (const float*)d_in[15];
    const float* wm2  = (const float*)d_in[16];
    const float* bm2  = (const float*)d_in[17];
    const float* wout = (const float*)d_in[18];
    const float* bout = (const float*)d_in[19];
    float* out = (float*)d_out;

    float *p_hidden, *p_map1, *p_ti, *p_enc, *p_bht;
    __nv_bfloat16 *p_emb_h, *p_emb_l, *p_tw_h, *p_tw_l, *p_hid_h, *p_hid_l;
    __nv_bfloat16 *p_dep_h, *p_dep_l, *p_enc_h, *p_enc_l;
    __nv_bfloat16 *p_w1h, *p_w1l, *p_whth, *p_whtl;
    __nv_bfloat16 *p_wm1h, *p_wm1l, *p_wtih, *p_wtil, *p_wgh, *p_wgl;
    __half *p_w16;
    cudaGetSymbolAddress((void**)&p_hidden, g_hidden);
    cudaGetSymbolAddress((void**)&p_map1,   g_map1);
    cudaGetSymbolAddress((void**)&p_ti,     g_ti);
    cudaGetSymbolAddress((void**)&p_enc,    g_enc);
    cudaGetSymbolAddress((void**)&p_bht,    g_bht);
    cudaGetSymbolAddress((void**)&p_emb_h,  g_emb_hi);
    cudaGetSymbolAddress((void**)&p_emb_l,  g_emb_lo);
    cudaGetSymbolAddress((void**)&p_tw_h,   g_tw_hi);
    cudaGetSymbolAddress((void**)&p_tw_l,   g_tw_lo);
    cudaGetSymbolAddress((void**)&p_hid_h,  g_hid_hi);
    cudaGetSymbolAddress((void**)&p_hid_l,  g_hid_lo);
    cudaGetSymbolAddress((void**)&p_dep_h,  g_dep_hi);
    cudaGetSymbolAddress((void**)&p_dep_l,  g_dep_lo);
    cudaGetSymbolAddress((void**)&p_enc_h,  g_enc_hi);
    cudaGetSymbolAddress((void**)&p_enc_l,  g_enc_lo);
    cudaGetSymbolAddress((void**)&p_w1h,    g_w1T_h);
    cudaGetSymbolAddress((void**)&p_w1l,    g_w1T_l);
    cudaGetSymbolAddress((void**)&p_whth,   g_whtT_h);
    cudaGetSymbolAddress((void**)&p_whtl,   g_whtT_l);
    cudaGetSymbolAddress((void**)&p_wm1h,   g_wm1T_h);
    cudaGetSymbolAddress((void**)&p_wm1l,   g_wm1T_l);
    cudaGetSymbolAddress((void**)&p_wtih,   g_wtiT_h);
    cudaGetSymbolAddress((void**)&p_wtil,   g_wtiT_l);
    cudaGetSymbolAddress((void**)&p_wgh,    g_wgT_h);
    cudaGetSymbolAddress((void**)&p_wgl,    g_wgT_l);
    cudaGetSymbolAddress((void**)&p_w16,    g_w16);

    cudaFuncSetAttribute(mgemm_k<1>, cudaFuncAttributeMaxDynamicSharedMemorySize, SMEM_MG);
    cudaFuncSetAttribute(mgemm_k<2>, cudaFuncAttributeMaxDynamicSharedMemorySize, SMEM_MG);
    cudaFuncSetAttribute(mgemm_k<3>, cudaFuncAttributeMaxDynamicSharedMemorySize, SMEM_MG);
    cudaFuncSetAttribute(mgemm_k<5>, cudaFuncAttributeMaxDynamicSharedMemorySize, SMEM_MG);
    cudaFuncSetAttribute(attnmma_k,  cudaFuncAttributeMaxDynamicSharedMemorySize, SMEM_AT);
    cudaFuncSetAttribute(fgemm_k,    cudaFuncAttributeMaxDynamicSharedMemorySize, SMEM_FG);

    caslen_k<<<Bc, 256>>>(cas);
    concatBias_k<<<4, 256>>>(bh, bt);

    // weight preprocessing
    transW_f16_k<<<dim3(Vdim/32, Hdim/32), dim3(32,8)>>>(wout, p_w16);
    transW_bf16_k<<<dim3(16,16), dim3(32,8)>>>(w1,  p_w1h,  p_w1l,  Hdim);
    transW_bf16_k<<<dim3(16,16), dim3(32,8)>>>(wh,  p_whth, p_whtl, Hdim);
    transW_bf16_k<<<dim3(16,16), dim3(32,8)>>>(wt,  p_whth + Hdim*Hdim, p_whtl + Hdim*Hdim, Hdim);
    transW_bf16_k<<<dim3(16,16), dim3(32,8)>>>(wm1, p_wm1h, p_wm1l, Hdim);
    transW_bf16_k<<<dim3(16,16), dim3(32,8)>>>(wti, p_wtih, p_wtil, Hdim);
    transW_bf16_k<<<dim3(16,32), dim3(32,8)>>>(wg,  p_wgh,  p_wgl,  2*Hdim);

    // activation gathers + splits
    gatherSplit_k<<<(Mrows*Hdim)/256, 256>>>(emb,  cas, p_emb_h, p_emb_l);
    gatherSplit_k<<<(Mrows*Hdim)/256, 256>>>(tlam, tii, p_tw_h,  p_tw_l);

    dim3 gmid(Hdim/MGN, Mrows/MGM);    // (4, 50)
    // hidden = elu(emb@w1+b1)*mask (fp32 + splits)
    mgemm_k<1><<<gmid, 256, SMEM_MG>>>(p_emb_h, p_emb_l, p_emb_h, p_emb_l,
                                       p_w1h, p_w1l, Hdim, 8, b1,
                                       p_hidden, p_hid_h, p_hid_l);
    // hidden^T for attention GEMM2
    transHid_k<<<dim3(7, 16, Bc), dim3(32,8)>>>();
    // head+tail merged: N=1024, grid (8, 50)
    mgemm_k<5><<<dim3(8, Mrows/MGM), 256, SMEM_MG>>>(p_hid_h, p_hid_l, p_hid_h, p_hid_l,
                                       p_whth, p_whtl, Hdim, 8, p_bht,
                                       nullptr, nullptr, nullptr);
    // attention via mma -> depend (fp32 + splits)
    attnmma_k<<<dim3(4, Bc), 256, SMEM_AT>>>();
    // gate -> enc (fp32 + splits)
    mgemm_k<3><<<gmid, 256, SMEM_MG>>>(p_hid_h, p_hid_l, p_dep_h, p_dep_l,
                                       p_wgh, p_wgl, 2*Hdim, 16, bg,
                                       p_enc, p_enc_h, p_enc_l);
    // map1, ti
    mgemm_k<2><<<gmid, 256, SMEM_MG>>>(p_enc_h, p_enc_l, p_enc_h, p_enc_l,
                                       p_wm1h, p_wm1l, Hdim, 8, bm1,
                                       p_map1, nullptr, nullptr);
    mgemm_k<2><<<gmid, 256, SMEM_MG>>>(p_tw_h, p_tw_l, p_tw_h, p_tw_l,
                                       p_wtih, p_wtil, Hdim, 8, bti,
                                       p_ti, nullptr, nullptr);
    // pool -> a16
    pool_k<<<Bc, 256>>>(wm2, bm2);
    // final GEMM (R9 config: 128x128, 2 CTAs/SM)
    fgemm_k<<<dim3(Vdim/128, Mrows/128), 256, SMEM_FG>>>(bout, out);
}